// round 13
// baseline (speedup 1.0000x reference)
#include <cuda_runtime.h>
#include <cstdint>

#define T_STEPS 256
#define BATCH   8
#define NPROBES 4
#define CLUSTER 8
#define ROWS_PER_CTA (128 / CLUSTER)      // 16
#define NWARPS  ROWS_PER_CTA              // 16
#define NTHREADS (NWARPS * 32)            // 512
#define NCTAS   (BATCH * CLUSTER)         // 64
#define FULLM   0xffffffffu

typedef unsigned long long ull;

// ---------- f32x2 packed helpers (sm_103a) ----------
__device__ __forceinline__ ull pack2(float lo, float hi) {
    ull r; asm("mov.b64 %0, {%1, %2};" : "=l"(r) : "f"(lo), "f"(hi)); return r;
}
__device__ __forceinline__ void unpack2(ull a, float& lo, float& hi) {
    asm("mov.b64 {%0, %1}, %2;" : "=f"(lo), "=f"(hi) : "l"(a));
}
__device__ __forceinline__ ull add2(ull a, ull b) {
    ull r; asm("add.rn.f32x2 %0, %1, %2;" : "=l"(r) : "l"(a), "l"(b)); return r;
}
__device__ __forceinline__ ull fma2(ull a, ull b, ull c) {
    ull r; asm("fma.rn.f32x2 %0, %1, %2, %3;" : "=l"(r) : "l"(a), "l"(b), "l"(c)); return r;
}

// ---------- cluster / mbarrier helpers ----------
__device__ __forceinline__ uint32_t smem_u32(const void* p) {
    uint32_t a;
    asm("{ .reg .u64 t; cvta.to.shared.u64 t, %1; cvt.u32.u64 %0, t; }" : "=r"(a) : "l"(p));
    return a;
}
__device__ __forceinline__ uint32_t mapa_u32(uint32_t addr, uint32_t rank) {
    uint32_t r; asm("mapa.shared::cluster.u32 %0, %1, %2;" : "=r"(r) : "r"(addr), "r"(rank));
    return r;
}
__device__ __forceinline__ void st_cluster_v2(uint32_t addr, ull a, ull b) {
    asm volatile("st.shared::cluster.v2.u64 [%0], {%1, %2};" :: "r"(addr), "l"(a), "l"(b) : "memory");
}
__device__ __forceinline__ void mbar_init(uint32_t addr, uint32_t cnt) {
    asm volatile("mbarrier.init.shared.b64 [%0], %1;" :: "r"(addr), "r"(cnt) : "memory");
}
__device__ __forceinline__ void mbar_arrive_local(uint32_t addr) {
    asm volatile("mbarrier.arrive.release.cta.shared::cta.b64 _, [%0];" :: "r"(addr) : "memory");
}
__device__ __forceinline__ void mbar_arrive_remote(uint32_t addr) {
    asm volatile("mbarrier.arrive.release.cluster.shared::cluster.b64 _, [%0];" :: "r"(addr) : "memory");
}
__device__ __forceinline__ void mbar_wait_cta(uint32_t addr, uint32_t ph) {
    uint32_t done;
    do {
        asm volatile("{\n\t.reg .pred p;\n\t"
                     "mbarrier.try_wait.parity.acquire.cta.shared::cta.b64 p, [%1], %2, 0x989680;\n\t"
                     "selp.b32 %0, 1, 0, p;\n\t}"
                     : "=r"(done) : "r"(addr), "r"(ph) : "memory");
    } while (!done);
}
__device__ __forceinline__ void mbar_wait_cluster(uint32_t addr, uint32_t ph) {
    uint32_t done;
    do {
        asm volatile("{\n\t.reg .pred p;\n\t"
                     "mbarrier.try_wait.parity.acquire.cluster.shared::cta.b64 p, [%1], %2, 0x989680;\n\t"
                     "selp.b32 %0, 1, 0, p;\n\t}"
                     : "=r"(done) : "r"(addr), "r"(ph) : "memory");
    } while (!done);
}
__device__ __forceinline__ void cluster_sync() {
    asm volatile("barrier.cluster.arrive.aligned;" ::: "memory");
    asm volatile("barrier.cluster.wait.aligned;"   ::: "memory");
}

__device__ float    g_psum[NPROBES] = {0.f, 0.f, 0.f, 0.f};
__device__ unsigned g_ticket        = 0u;

// dynamic smem (bytes):
//   [0, 16384)      halo  : ull[2][16][64]
//   [16384, 17408)  rbufA : ull[2][64]
//   [17408, 18432)  rbufB : ull[2][64]
//   [18432, 19456)  xsh   : float[256]
//   [19456, 19712)  wmbar : ull[16][2]
#define OFF_RBUFA 16384
#define OFF_RBUFB 17408
#define OFF_XSH   18432
#define OFF_WMBAR 19456
#define SMEM_BYTES 19728
#define HSTRIDE (ROWS_PER_CTA * 64)       // ull per halo buffer

__global__ __launch_bounds__(NTHREADS, 1) __cluster_dims__(CLUSTER, 1, 1)
void wave_fused_kernel(const float* __restrict__ x,
                       const float* __restrict__ c,
                       const int* __restrict__ probes_i32,
                       float* __restrict__ out)
{
    extern __shared__ char smem_raw[];
    ull*   halo  = reinterpret_cast<ull*>(smem_raw);
    ull*   rbufA = reinterpret_cast<ull*>(smem_raw + OFF_RBUFA);
    ull*   rbufB = reinterpret_cast<ull*>(smem_raw + OFF_RBUFB);
    float* xsh   = reinterpret_cast<float*>(smem_raw + OFF_XSH);

    const uint32_t smem_base  = smem_u32(smem_raw);
    const uint32_t wmbar_base = smem_base + OFF_WMBAR;

    uint32_t rank; asm("mov.u32 %0, %%cluster_ctarank;" : "=r"(rank));
    const int b   = blockIdx.x / CLUSTER;
    const int tid = threadIdx.x;
    const int w   = tid >> 5;
    const int l   = tid & 31;
    const int c0  = l << 2;
    const int gr  = (int)rank * ROWS_PER_CTA + w;

    const float dtb   = 0.5f * 0.005f;
    const float cy2s  = -1.0f - dtb;                   // -1.0025
    const float denom = 4.0f + (0.5f * 0.005f) / 0.5f; // 4.005
    const float invd  = 1.0f / denom;

    const ull NEG4  = pack2(-4.0f, -4.0f);
    const ull CY2P  = pack2(cy2s * invd, cy2s * invd);
    const ull TWO2P = pack2(2.0f * invd, 2.0f * invd);

    for (int t = tid; t < T_STEPS; t += NTHREADS)
        xsh[t] = x[t * BATCH + b];
    for (int i = tid; i < 2 * HSTRIDE; i += NTHREADS)
        halo[i] = 0ull;
    for (int i = tid; i < 2 * 64; i += NTHREADS) { rbufA[i] = 0ull; rbufB[i] = 0ull; }

    ull kkx, kky, y1lo, y1hi, y2lo, y2hi;
    {
        float4 cv = *reinterpret_cast<const float4*>(&c[gr * 128 + c0]);
        kkx = pack2(0.25f * cv.x * cv.x * invd, 0.25f * cv.y * cv.y * invd);
        kky = pack2(0.25f * cv.z * cv.z * invd, 0.25f * cv.w * cv.w * invd);
        y1lo = 0ull; y1hi = 0ull; y2lo = 0ull; y2hi = 0ull;
    }

    // ---- probe decoding (runtime dtype detection: int32 vs int64) ----
    int pxv[NPROBES], pyv[NPROBES];
    {
        int odd_or = probes_i32[1] | probes_i32[3] | probes_i32[5] | probes_i32[7];
        if (odd_or == 0) {
#pragma unroll
            for (int p = 0; p < NPROBES; p++) { pxv[p] = probes_i32[4 * p]; pyv[p] = probes_i32[4 * p + 2]; }
        } else {
#pragma unroll
            for (int p = 0; p < NPROBES; p++) { pxv[p] = probes_i32[2 * p]; pyv[p] = probes_i32[2 * p + 1]; }
        }
    }
    float pacc[NPROBES];
    int   pidx[NPROBES];
    bool  pown = false;
#pragma unroll
    for (int p = 0; p < NPROBES; p++) {
        pacc[p] = 0.f;
        bool mine = (pxv[p] == gr) && (pyv[p] >= c0) && (pyv[p] < c0 + 4);
        pidx[p] = mine ? (pyv[p] - c0) : -1;
        pown = pown || mine;
    }

    const bool src_owner = (rank == 4) && (w == 0) && (l == 16);

    const bool top_edge = (w == 0)          && (rank > 0);
    const bool bot_edge = (w == NWARPS - 1) && (rank < CLUSTER - 1);
    const uint32_t up_rank = (rank > 0) ? rank - 1 : 0;
    const uint32_t dn_rank = (rank < CLUSTER - 1) ? rank + 1 : rank;
    const uint32_t peer_up_rbuf = mapa_u32(smem_base + OFF_RBUFB, up_rank) + (2 * l) * 8;
    const uint32_t peer_up_mbar = mapa_u32(wmbar_base + ((NWARPS - 1) * 2) * 8, up_rank);
    const uint32_t peer_dn_rbuf = mapa_u32(smem_base + OFF_RBUFA, dn_rank) + (2 * l) * 8;
    const uint32_t peer_dn_mbar = mapa_u32(wmbar_base + (0 * 2) * 8, dn_rank);

    const uint32_t my_mbar = wmbar_base + (w * 2) * 8;
    const uint32_t up_mbar = wmbar_base + ((w - 1) * 2) * 8;
    const uint32_t dn_mbar = wmbar_base + ((w + 1) * 2) * 8;

    if (l == 0) {
        uint32_t cnt = 0;
        cnt += (w > 0 || rank > 0) ? 32 : 0;
        cnt += (w < NWARPS - 1 || rank < CLUSTER - 1) ? 32 : 0;
        mbar_init(my_mbar, cnt);
        mbar_init(my_mbar + 8, cnt);
    }
    const bool has_remote = top_edge || bot_edge;
    const bool has_up     = (w > 0);
    const bool has_dn     = (w < NWARPS - 1);

    // hoisted base pointers (buffer offset applied as literal in unrolled body)
    ull* const hp_ab = &halo[(w - 1) * 64 + 2 * l];   // valid only if has_up
    ull* const hp_bl = &halo[(w + 1) * 64 + 2 * l];   // valid only if has_dn
    ull* const hp_my = &halo[w * 64 + 2 * l];
    ull* const rpA   = &rbufA[2 * l];
    ull* const rpB   = &rbufB[2 * l];

    __syncthreads();
    cluster_sync();

    int ph0 = 0, ph1 = 0;   // phases for wait slots 0 and 1

    // one simulation step; RD/WR are compile-time buffer selectors after inlining
    auto body = [&](int t, int RD, int WR, int ph) {
        // wait for both neighbors' step-(t-1) data (slot = RD)
        if (t > 0) {
            const uint32_t mb = my_mbar + RD * 8;
            if (has_remote) mbar_wait_cluster(mb, ph);
            else            mbar_wait_cta(mb, ph);
        }

        ull ab_lo = 0, ab_hi = 0, bl_lo = 0, bl_hi = 0;
        if (has_up) {
            ulonglong2 h = *reinterpret_cast<const ulonglong2*>(hp_ab + RD * HSTRIDE);
            ab_lo = h.x; ab_hi = h.y;
        } else if (top_edge) {
            ulonglong2 h = *reinterpret_cast<const ulonglong2*>(rpA + RD * 64);
            ab_lo = h.x; ab_hi = h.y;
        }
        if (has_dn) {
            ulonglong2 h = *reinterpret_cast<const ulonglong2*>(hp_bl + RD * HSTRIDE);
            bl_lo = h.x; bl_hi = h.y;
        } else if (bot_edge) {
            ulonglong2 h = *reinterpret_cast<const ulonglong2*>(rpB + RD * 64);
            bl_lo = h.x; bl_hi = h.y;
        }

        const ull v_lo = y1lo, v_hi = y1hi;
        float vx, vy, vz, vw;
        unpack2(v_lo, vx, vy);
        unpack2(v_hi, vz, vw);

        float lf = __shfl_up_sync(FULLM, vw, 1);
        float rt = __shfl_down_sync(FULLM, vx, 1);
        if (l == 0)  lf = 0.f;
        if (l == 31) rt = 0.f;

        const ull P1 = pack2(lf, vx);
        const ull P2 = pack2(vy, vz);
        const ull P3 = pack2(vw, rt);

        ull lap_lo = add2(add2(ab_lo, bl_lo), add2(P1, P2));
        lap_lo = fma2(NEG4, v_lo, lap_lo);
        ull lap_hi = add2(add2(ab_hi, bl_hi), add2(P2, P3));
        lap_hi = fma2(NEG4, v_hi, lap_hi);

        ull nv_lo = fma2(kkx, lap_lo, fma2(CY2P, y2lo, TWO2P));
        ull nv_hi = fma2(kky, lap_hi, fma2(CY2P, y2hi, TWO2P));

        if (src_owner) {
            float a, b2; unpack2(nv_lo, a, b2);
            nv_lo = pack2(a + xsh[t], b2);
        }

        y2lo = v_lo;  y2hi = v_hi;
        y1lo = nv_lo; y1hi = nv_hi;

        // publish first (neighbor wakeups start ASAP), probes after
        if (t < T_STEPS - 1) {
            ulonglong2 rv; rv.x = y1lo; rv.y = y1hi;
            *reinterpret_cast<ulonglong2*>(hp_my + WR * HSTRIDE) = rv;

            if (has_up) mbar_arrive_local(up_mbar + WR * 8);
            if (has_dn) mbar_arrive_local(dn_mbar + WR * 8);

            if (top_edge) {
                st_cluster_v2(peer_up_rbuf + WR * 512, y1lo, y1hi);
                mbar_arrive_remote(peer_up_mbar + WR * 8);
            }
            if (bot_edge) {
                st_cluster_v2(peer_dn_rbuf + WR * 512, y1lo, y1hi);
                mbar_arrive_remote(peer_dn_mbar + WR * 8);
            }
        }

        if (pown) {
#pragma unroll
            for (int p = 0; p < NPROBES; p++) {
                if (pidx[p] >= 0) {
                    float a, bf, val = 0.f;
                    switch (pidx[p]) {
                        case 0: unpack2(y1lo, a, bf); val = a;  break;
                        case 1: unpack2(y1lo, a, bf); val = bf; break;
                        case 2: unpack2(y1hi, a, bf); val = a;  break;
                        case 3: unpack2(y1hi, a, bf); val = bf; break;
                    }
                    pacc[p] += val * val;
                }
            }
        }
    };

    for (int tt = 0; tt < T_STEPS; tt += 2) {
        // even step t=tt:   reads buf 1 (slot 1), writes buf 0
        body(tt, 1, 0, ph1);
        if (tt > 0) ph1 ^= 1;        // slot-1 phase flips after each use (first use t=2 has ph1=0)
        // odd step t=tt+1:  reads buf 0 (slot 0), writes buf 1
        body(tt + 1, 0, 1, ph0);
        ph0 ^= 1;                    // slot-0 phase flips after each use (first use t=1 has ph0=0)
    }

#pragma unroll
    for (int p = 0; p < NPROBES; p++)
        if (pidx[p] >= 0) atomicAdd(&g_psum[p], pacc[p]);

    __syncthreads();
    __threadfence();
    if (tid == 0) {
        unsigned ticket = atomicAdd(&g_ticket, 1u);
        if (ticket == NCTAS - 1) {
            float v[NPROBES];
            float s = 0.f;
#pragma unroll
            for (int p = 0; p < NPROBES; p++) { v[p] = atomicAdd(&g_psum[p], 0.0f); s += v[p]; }
#pragma unroll
            for (int p = 0; p < NPROBES; p++) {
                out[p] = v[p] / s;
                atomicExch(&g_psum[p], 0.0f);
            }
            atomicExch(&g_ticket, 0u);
        }
    }
}

extern "C" void kernel_launch(void* const* d_in, const int* in_sizes, int n_in,
                              void* d_out, int out_size)
{
    const float* x      = (const float*)d_in[0];   // (256, 8) f32
    const float* c      = (const float*)d_in[1];   // (128, 128) f32
    const int*   probes = (const int*)d_in[2];     // (4, 2) i32/i64 — detected in-kernel
    float*       out    = (float*)d_out;           // (4,) f32

    cudaFuncSetAttribute(wave_fused_kernel,
                         cudaFuncAttributeMaxDynamicSharedMemorySize, SMEM_BYTES);

    wave_fused_kernel<<<NCTAS, NTHREADS, SMEM_BYTES>>>(x, c, probes, out);
}

// round 14
// speedup vs baseline: 1.0448x; 1.0448x over previous
#include <cuda_runtime.h>
#include <cstdint>

#define T_STEPS 256
#define BATCH   8
#define NPROBES 4
#define CLUSTER 8
#define ROWS_PER_CTA (128 / CLUSTER)      // 16
#define NWARPS  ROWS_PER_CTA              // 16
#define NTHREADS (NWARPS * 32)            // 512
#define NCTAS   (BATCH * CLUSTER)         // 64
#define FULLM   0xffffffffu

typedef unsigned long long ull;

// ---------- f32x2 packed helpers (sm_103a) ----------
__device__ __forceinline__ ull pack2(float lo, float hi) {
    ull r; asm("mov.b64 %0, {%1, %2};" : "=l"(r) : "f"(lo), "f"(hi)); return r;
}
__device__ __forceinline__ void unpack2(ull a, float& lo, float& hi) {
    asm("mov.b64 {%0, %1}, %2;" : "=f"(lo), "=f"(hi) : "l"(a));
}
__device__ __forceinline__ ull add2(ull a, ull b) {
    ull r; asm("add.rn.f32x2 %0, %1, %2;" : "=l"(r) : "l"(a), "l"(b)); return r;
}
__device__ __forceinline__ ull fma2(ull a, ull b, ull c) {
    ull r; asm("fma.rn.f32x2 %0, %1, %2, %3;" : "=l"(r) : "l"(a), "l"(b), "l"(c)); return r;
}

// ---------- cluster / mbarrier helpers ----------
__device__ __forceinline__ uint32_t smem_u32(const void* p) {
    uint32_t a;
    asm("{ .reg .u64 t; cvta.to.shared.u64 t, %1; cvt.u32.u64 %0, t; }" : "=r"(a) : "l"(p));
    return a;
}
__device__ __forceinline__ uint32_t mapa_u32(uint32_t addr, uint32_t rank) {
    uint32_t r; asm("mapa.shared::cluster.u32 %0, %1, %2;" : "=r"(r) : "r"(addr), "r"(rank));
    return r;
}
__device__ __forceinline__ void st_cluster_v2(uint32_t addr, ull a, ull b) {
    asm volatile("st.shared::cluster.v2.u64 [%0], {%1, %2};" :: "r"(addr), "l"(a), "l"(b) : "memory");
}
__device__ __forceinline__ void mbar_init(uint32_t addr, uint32_t cnt) {
    asm volatile("mbarrier.init.shared.b64 [%0], %1;" :: "r"(addr), "r"(cnt) : "memory");
}
__device__ __forceinline__ void mbar_arrive_local(uint32_t addr) {
    asm volatile("mbarrier.arrive.release.cta.shared::cta.b64 _, [%0];" :: "r"(addr) : "memory");
}
__device__ __forceinline__ void mbar_arrive_remote(uint32_t addr) {
    asm volatile("mbarrier.arrive.release.cluster.shared::cluster.b64 _, [%0];" :: "r"(addr) : "memory");
}
__device__ __forceinline__ void mbar_wait_cta(uint32_t addr, uint32_t ph) {
    uint32_t done;
    do {
        asm volatile("{\n\t.reg .pred p;\n\t"
                     "mbarrier.try_wait.parity.acquire.cta.shared::cta.b64 p, [%1], %2, 0x989680;\n\t"
                     "selp.b32 %0, 1, 0, p;\n\t}"
                     : "=r"(done) : "r"(addr), "r"(ph) : "memory");
    } while (!done);
}
__device__ __forceinline__ void mbar_wait_cluster(uint32_t addr, uint32_t ph) {
    uint32_t done;
    do {
        asm volatile("{\n\t.reg .pred p;\n\t"
                     "mbarrier.try_wait.parity.acquire.cluster.shared::cta.b64 p, [%1], %2, 0x989680;\n\t"
                     "selp.b32 %0, 1, 0, p;\n\t}"
                     : "=r"(done) : "r"(addr), "r"(ph) : "memory");
    } while (!done);
}
__device__ __forceinline__ void cluster_sync() {
    asm volatile("barrier.cluster.arrive.aligned;" ::: "memory");
    asm volatile("barrier.cluster.wait.aligned;"   ::: "memory");
}

__device__ float    g_psum[NPROBES] = {0.f, 0.f, 0.f, 0.f};
__device__ unsigned g_ticket        = 0u;

// dynamic smem (bytes):
//   [0, 16384)      halo  : ull[2][16][64]
//   [16384, 17408)  rbufA : ull[2][64]
//   [17408, 18432)  rbufB : ull[2][64]
//   [18432, 19456)  xsh   : float[256]
//   [19456, 19712)  wmbar : ull[16][2]
#define OFF_RBUFA 16384
#define OFF_RBUFB 17408
#define OFF_XSH   18432
#define OFF_WMBAR 19456
#define SMEM_BYTES 19728

__global__ __launch_bounds__(NTHREADS, 1) __cluster_dims__(CLUSTER, 1, 1)
void wave_fused_kernel(const float* __restrict__ x,
                       const float* __restrict__ c,
                       const int* __restrict__ probes_i32,
                       float* __restrict__ out)
{
    extern __shared__ char smem_raw[];
    ull*   halo  = reinterpret_cast<ull*>(smem_raw);
    ull*   rbufA = reinterpret_cast<ull*>(smem_raw + OFF_RBUFA);
    ull*   rbufB = reinterpret_cast<ull*>(smem_raw + OFF_RBUFB);
    float* xsh   = reinterpret_cast<float*>(smem_raw + OFF_XSH);

    const uint32_t smem_base  = smem_u32(smem_raw);
    const uint32_t wmbar_base = smem_base + OFF_WMBAR;   // wmbar[w][bi] at +(w*2+bi)*8

    uint32_t rank; asm("mov.u32 %0, %%cluster_ctarank;" : "=r"(rank));
    const int b   = blockIdx.x / CLUSTER;     // batch = cluster id
    const int tid = threadIdx.x;
    const int w   = tid >> 5;                 // warp 0..15 : local row w
    const int l   = tid & 31;                 // lane       : cols 4l..4l+3
    const int c0  = l << 2;
    const int gr  = (int)rank * ROWS_PER_CTA + w;   // my global row

    // constants (reference-exact, folded by invd)
    const float dtb   = 0.5f * 0.005f;
    const float cy2s  = -1.0f - dtb;                   // -1.0025
    const float denom = 4.0f + (0.5f * 0.005f) / 0.5f; // 4.005
    const float invd  = 1.0f / denom;

    const ull NEG4  = pack2(-4.0f, -4.0f);
    const ull CY2P  = pack2(cy2s * invd, cy2s * invd);
    const ull TWO2P = pack2(2.0f * invd, 2.0f * invd);

    for (int t = tid; t < T_STEPS; t += NTHREADS)
        xsh[t] = x[t * BATCH + b];
    for (int i = tid; i < 2 * ROWS_PER_CTA * 64; i += NTHREADS)
        halo[i] = 0ull;
    for (int i = tid; i < 2 * 64; i += NTHREADS) { rbufA[i] = 0ull; rbufB[i] = 0ull; }

    // kk' = 0.25*c^2*invd for my single row
    ull kkx, kky, y1lo, y1hi, y2lo, y2hi;
    {
        float4 cv = *reinterpret_cast<const float4*>(&c[gr * 128 + c0]);
        kkx = pack2(0.25f * cv.x * cv.x * invd, 0.25f * cv.y * cv.y * invd);
        kky = pack2(0.25f * cv.z * cv.z * invd, 0.25f * cv.w * cv.w * invd);
        y1lo = 0ull; y1hi = 0ull; y2lo = 0ull; y2hi = 0ull;
    }

    // ---- probe decoding (runtime dtype detection: int32 vs int64) ----
    int pxv[NPROBES], pyv[NPROBES];
    {
        int odd_or = probes_i32[1] | probes_i32[3] | probes_i32[5] | probes_i32[7];
        if (odd_or == 0) {
#pragma unroll
            for (int p = 0; p < NPROBES; p++) { pxv[p] = probes_i32[4 * p]; pyv[p] = probes_i32[4 * p + 2]; }
        } else {
#pragma unroll
            for (int p = 0; p < NPROBES; p++) { pxv[p] = probes_i32[2 * p]; pyv[p] = probes_i32[2 * p + 1]; }
        }
    }
    float pacc[NPROBES];
    int   pidx[NPROBES];          // comp 0..3, or -1
    bool  pown = false;
#pragma unroll
    for (int p = 0; p < NPROBES; p++) {
        pacc[p] = 0.f;
        bool mine = (pxv[p] == gr) && (pyv[p] >= c0) && (pyv[p] < c0 + 4);
        pidx[p] = mine ? (pyv[p] - c0) : -1;
        pown = pown || mine;
    }

    // source (64,64): global row 64 = rank 4, w 0; col 64 -> lane 16, comp 0
    const bool src_owner = (rank == 4) && (w == 0) && (l == 16);

    // cluster seam roles
    const bool top_edge = (w == 0)          && (rank > 0);            // reads rbufA, pushes up
    const bool bot_edge = (w == NWARPS - 1) && (rank < CLUSTER - 1);  // reads rbufB, pushes down
    const uint32_t up_rank = (rank > 0) ? rank - 1 : 0;
    const uint32_t dn_rank = (rank < CLUSTER - 1) ? rank + 1 : rank;
    const uint32_t peer_up_rbuf  = mapa_u32(smem_base + OFF_RBUFB, up_rank);
    const uint32_t peer_up_mbar  = mapa_u32(wmbar_base + ((NWARPS - 1) * 2) * 8, up_rank);
    const uint32_t peer_dn_rbuf  = mapa_u32(smem_base + OFF_RBUFA, dn_rank);
    const uint32_t peer_dn_mbar  = mapa_u32(wmbar_base + (0 * 2) * 8, dn_rank);

    const uint32_t my_mbar = wmbar_base + (w * 2) * 8;
    const uint32_t up_mbar = wmbar_base + ((w - 1) * 2) * 8;
    const uint32_t dn_mbar = wmbar_base + ((w + 1) * 2) * 8;

    // init my two mbars: ONE elected arrive per producer warp feeding me
    if (l == 0) {
        uint32_t cnt = 0;
        cnt += (w > 0 || rank > 0) ? 1 : 0;                          // above producer
        cnt += (w < NWARPS - 1 || rank < CLUSTER - 1) ? 1 : 0;       // below producer
        mbar_init(my_mbar, cnt);
        mbar_init(my_mbar + 8, cnt);
    }
    const bool has_remote = top_edge || bot_edge;
    const bool has_up     = (w > 0);
    const bool has_dn     = (w < NWARPS - 1);

    __syncthreads();   // local init + smem zero done
    cluster_sync();    // visible cluster-wide before any remote arrive

    for (int t = 0; t < T_STEPS; t++) {
        const int rdbuf = (t + 1) & 1;   // buffer with step t-1 data
        const int wrbuf = t & 1;

        // single HW-sleep wait for both neighbors' step-(t-1) data
        if (t > 0) {
            const uint32_t mb = my_mbar + ((t - 1) & 1) * 8;
            const uint32_t ph = ((t - 1) >> 1) & 1;
            if (has_remote) mbar_wait_cluster(mb, ph);
            else            mbar_wait_cta(mb, ph);
        }

        // neighbor rows
        ull ab_lo = 0, ab_hi = 0, bl_lo = 0, bl_hi = 0;
        if (has_up) {
            ulonglong2 h = *reinterpret_cast<const ulonglong2*>(
                &halo[rdbuf * (ROWS_PER_CTA * 64) + (w - 1) * 64 + 2 * l]);
            ab_lo = h.x; ab_hi = h.y;
        } else if (top_edge) {
            ulonglong2 h = *reinterpret_cast<const ulonglong2*>(&rbufA[rdbuf * 64 + 2 * l]);
            ab_lo = h.x; ab_hi = h.y;
        }
        if (has_dn) {
            ulonglong2 h = *reinterpret_cast<const ulonglong2*>(
                &halo[rdbuf * (ROWS_PER_CTA * 64) + (w + 1) * 64 + 2 * l]);
            bl_lo = h.x; bl_hi = h.y;
        } else if (bot_edge) {
            ulonglong2 h = *reinterpret_cast<const ulonglong2*>(&rbufB[rdbuf * 64 + 2 * l]);
            bl_lo = h.x; bl_hi = h.y;
        }

        // update my row
        {
            const ull v_lo = y1lo, v_hi = y1hi;
            float vx, vy, vz, vw;
            unpack2(v_lo, vx, vy);
            unpack2(v_hi, vz, vw);

            float lf = __shfl_up_sync(FULLM, vw, 1);
            float rt = __shfl_down_sync(FULLM, vx, 1);
            if (l == 0)  lf = 0.f;
            if (l == 31) rt = 0.f;

            const ull P1 = pack2(lf, vx);
            const ull P2 = pack2(vy, vz);
            const ull P3 = pack2(vw, rt);

            ull lap_lo = add2(add2(ab_lo, bl_lo), add2(P1, P2));
            lap_lo = fma2(NEG4, v_lo, lap_lo);
            ull lap_hi = add2(add2(ab_hi, bl_hi), add2(P2, P3));
            lap_hi = fma2(NEG4, v_hi, lap_hi);

            ull nv_lo = fma2(kkx, lap_lo, fma2(CY2P, y2lo, TWO2P));
            ull nv_hi = fma2(kky, lap_hi, fma2(CY2P, y2hi, TWO2P));

            if (src_owner) {
                float a, b2; unpack2(nv_lo, a, b2);
                nv_lo = pack2(a + xsh[t], b2);
            }

            y2lo = v_lo;  y2hi = v_hi;
            y1lo = nv_lo; y1hi = nv_hi;
        }

        // publish my row; elected lane arrives on consumers (skip after last step)
        if (t < T_STEPS - 1) {
            ulonglong2 rv; rv.x = y1lo; rv.y = y1hi;
            *reinterpret_cast<ulonglong2*>(
                &halo[wrbuf * (ROWS_PER_CTA * 64) + w * 64 + 2 * l]) = rv;

            if (top_edge)
                st_cluster_v2(peer_up_rbuf + (wrbuf * 64 + 2 * l) * 8, y1lo, y1hi);
            if (bot_edge)
                st_cluster_v2(peer_dn_rbuf + (wrbuf * 64 + 2 * l) * 8, y1lo, y1hi);

            __syncwarp();   // all lanes' stores visible to lane 0 (release propagates them)

            if (l == 0) {
                if (has_up)     mbar_arrive_local(up_mbar + wrbuf * 8);
                if (has_dn)     mbar_arrive_local(dn_mbar + wrbuf * 8);
                if (top_edge)   mbar_arrive_remote(peer_up_mbar + wrbuf * 8);
                if (bot_edge)   mbar_arrive_remote(peer_dn_mbar + wrbuf * 8);
            }
        }

        // probe accumulation (<=4 owning threads)
        if (pown) {
#pragma unroll
            for (int p = 0; p < NPROBES; p++) {
                if (pidx[p] >= 0) {
                    float a, bf, val = 0.f;
                    switch (pidx[p]) {
                        case 0: unpack2(y1lo, a, bf); val = a;  break;
                        case 1: unpack2(y1lo, a, bf); val = bf; break;
                        case 2: unpack2(y1hi, a, bf); val = a;  break;
                        case 3: unpack2(y1hi, a, bf); val = bf; break;
                    }
                    pacc[p] += val * val;
                }
            }
        }
    }

#pragma unroll
    for (int p = 0; p < NPROBES; p++)
        if (pidx[p] >= 0) atomicAdd(&g_psum[p], pacc[p]);

    // fused finalization: last of 64 CTAs reduces, writes out, resets globals
    __syncthreads();
    __threadfence();
    if (tid == 0) {
        unsigned ticket = atomicAdd(&g_ticket, 1u);
        if (ticket == NCTAS - 1) {
            float v[NPROBES];
            float s = 0.f;
#pragma unroll
            for (int p = 0; p < NPROBES; p++) { v[p] = atomicAdd(&g_psum[p], 0.0f); s += v[p]; }
#pragma unroll
            for (int p = 0; p < NPROBES; p++) {
                out[p] = v[p] / s;
                atomicExch(&g_psum[p], 0.0f);
            }
            atomicExch(&g_ticket, 0u);
        }
    }
}

extern "C" void kernel_launch(void* const* d_in, const int* in_sizes, int n_in,
                              void* d_out, int out_size)
{
    const float* x      = (const float*)d_in[0];   // (256, 8) f32
    const float* c      = (const float*)d_in[1];   // (128, 128) f32
    const int*   probes = (const int*)d_in[2];     // (4, 2) i32/i64 — detected in-kernel
    float*       out    = (float*)d_out;           // (4,) f32

    cudaFuncSetAttribute(wave_fused_kernel,
                         cudaFuncAttributeMaxDynamicSharedMemorySize, SMEM_BYTES);

    wave_fused_kernel<<<NCTAS, NTHREADS, SMEM_BYTES>>>(x, c, probes, out);
}

// round 15
// speedup vs baseline: 1.3499x; 1.2921x over previous
#include <cuda_runtime.h>
#include <cstdint>

#define T_STEPS 256
#define NBLK    (T_STEPS / 2)            // 128 two-step blocks
#define BATCH   8
#define NPROBES 4
#define CLUSTER 8
#define ROWS_PER_CTA 16
#define NWARPS  8                        // warp owns rows 2w, 2w+1 (local)
#define NTHREADS (NWARPS * 32)           // 256
#define NCTAS   (BATCH * CLUSTER)        // 64
#define FULLM   0xffffffffu

typedef unsigned long long ull;

// ---------- f32x2 packed helpers (sm_103a) ----------
__device__ __forceinline__ ull pack2(float lo, float hi) {
    ull r; asm("mov.b64 %0, {%1, %2};" : "=l"(r) : "f"(lo), "f"(hi)); return r;
}
__device__ __forceinline__ void unpack2(ull a, float& lo, float& hi) {
    asm("mov.b64 {%0, %1}, %2;" : "=f"(lo), "=f"(hi) : "l"(a));
}
__device__ __forceinline__ ull add2(ull a, ull b) {
    ull r; asm("add.rn.f32x2 %0, %1, %2;" : "=l"(r) : "l"(a), "l"(b)); return r;
}
__device__ __forceinline__ ull fma2(ull a, ull b, ull c) {
    ull r; asm("fma.rn.f32x2 %0, %1, %2, %3;" : "=l"(r) : "l"(a), "l"(b), "l"(c)); return r;
}

// ---------- cluster / mbarrier helpers ----------
__device__ __forceinline__ uint32_t smem_u32(const void* p) {
    uint32_t a;
    asm("{ .reg .u64 t; cvta.to.shared.u64 t, %1; cvt.u32.u64 %0, t; }" : "=r"(a) : "l"(p));
    return a;
}
__device__ __forceinline__ uint32_t mapa_u32(uint32_t addr, uint32_t rank) {
    uint32_t r; asm("mapa.shared::cluster.u32 %0, %1, %2;" : "=r"(r) : "r"(addr), "r"(rank));
    return r;
}
__device__ __forceinline__ void st_cluster_v2(uint32_t addr, ull a, ull b) {
    asm volatile("st.shared::cluster.v2.u64 [%0], {%1, %2};" :: "r"(addr), "l"(a), "l"(b) : "memory");
}
__device__ __forceinline__ void mbar_init(uint32_t addr, uint32_t cnt) {
    asm volatile("mbarrier.init.shared.b64 [%0], %1;" :: "r"(addr), "r"(cnt) : "memory");
}
__device__ __forceinline__ void mbar_arrive_local(uint32_t addr) {
    asm volatile("mbarrier.arrive.release.cta.shared::cta.b64 _, [%0];" :: "r"(addr) : "memory");
}
__device__ __forceinline__ void mbar_arrive_remote(uint32_t addr) {
    asm volatile("mbarrier.arrive.release.cluster.shared::cluster.b64 _, [%0];" :: "r"(addr) : "memory");
}
__device__ __forceinline__ void mbar_wait_cta(uint32_t addr, uint32_t ph) {
    uint32_t done;
    do {
        asm volatile("{\n\t.reg .pred p;\n\t"
                     "mbarrier.try_wait.parity.acquire.cta.shared::cta.b64 p, [%1], %2, 0x989680;\n\t"
                     "selp.b32 %0, 1, 0, p;\n\t}"
                     : "=r"(done) : "r"(addr), "r"(ph) : "memory");
    } while (!done);
}
__device__ __forceinline__ void mbar_wait_cluster(uint32_t addr, uint32_t ph) {
    uint32_t done;
    do {
        asm volatile("{\n\t.reg .pred p;\n\t"
                     "mbarrier.try_wait.parity.acquire.cluster.shared::cta.b64 p, [%1], %2, 0x989680;\n\t"
                     "selp.b32 %0, 1, 0, p;\n\t}"
                     : "=r"(done) : "r"(addr), "r"(ph) : "memory");
    } while (!done);
}
__device__ __forceinline__ void cluster_sync() {
    asm volatile("barrier.cluster.arrive.aligned;" ::: "memory");
    asm volatile("barrier.cluster.wait.aligned;"   ::: "memory");
}

__device__ float    g_psum[NPROBES] = {0.f, 0.f, 0.f, 0.f};
__device__ unsigned g_ticket        = 0u;

// dynamic smem (bytes):
//   [0, 32768)       halo  : ull[2][8][4][64]  slots: 0=a(t2) 1=b(t2) 2=a(t1) 3=b(t1)
//   [32768, 35840)   rbufA : ull[2][3][64]     from up-peer w7: a(t2), b(t2), b(t1)
//   [35840, 38912)   rbufB : ull[2][3][64]     from dn-peer w0: a(t2), b(t2), a(t1)
//   [38912, 39936)   xsh   : float[256]
//   [39936, 40064)   wmbar : ull[8][2]
#define OFF_RBUFA 32768
#define OFF_RBUFB 35840
#define OFF_XSH   38912
#define OFF_WMBAR 39936
#define SMEM_BYTES 40080

__global__ __launch_bounds__(NTHREADS, 1) __cluster_dims__(CLUSTER, 1, 1)
void wave_fused_kernel(const float* __restrict__ x,
                       const float* __restrict__ c,
                       const int* __restrict__ probes_i32,
                       float* __restrict__ out)
{
    extern __shared__ char smem_raw[];
    ull*   halo  = reinterpret_cast<ull*>(smem_raw);
    ull*   rbufA = reinterpret_cast<ull*>(smem_raw + OFF_RBUFA);
    ull*   rbufB = reinterpret_cast<ull*>(smem_raw + OFF_RBUFB);
    float* xsh   = reinterpret_cast<float*>(smem_raw + OFF_XSH);

    const uint32_t smem_base  = smem_u32(smem_raw);
    const uint32_t wmbar_base = smem_base + OFF_WMBAR;   // wmbar[w][bi] at +(w*2+bi)*8

    uint32_t rank; asm("mov.u32 %0, %%cluster_ctarank;" : "=r"(rank));
    const int b   = blockIdx.x / CLUSTER;
    const int tid = threadIdx.x;
    const int w   = tid >> 5;                 // warp 0..7 : local rows 2w, 2w+1
    const int l   = tid & 31;
    const int c0  = l << 2;
    const int ga  = (int)rank * ROWS_PER_CTA + 2 * w;   // global row of "a"
    const int gb  = ga + 1;                              // global row of "b"

    const float dtb   = 0.5f * 0.005f;
    const float cy2s  = -1.0f - dtb;                   // -1.0025
    const float denom = 4.0f + (0.5f * 0.005f) / 0.5f; // 4.005
    const float invd  = 1.0f / denom;

    const ull NEG4  = pack2(-4.0f, -4.0f);
    const ull CY2P  = pack2(cy2s * invd, cy2s * invd);
    const ull TWO2P = pack2(2.0f * invd, 2.0f * invd);

    for (int t = tid; t < T_STEPS; t += NTHREADS)
        xsh[t] = x[t * BATCH + b];
    for (int i = tid; i < 2 * 8 * 4 * 64; i += NTHREADS) halo[i]  = 0ull;
    for (int i = tid; i < 2 * 3 * 64;     i += NTHREADS) { rbufA[i] = 0ull; rbufB[i] = 0ull; }

    // kk' = 0.25*c^2*invd for rows a-1, a, b, b+1 (clamped at grid edges; edge values unused)
    ull kkm1x, kkm1y, kkax, kkay, kkbx, kkby, kkp1x, kkp1y;
    {
        int rm1 = (ga > 0) ? ga - 1 : 0;
        int rp1 = (gb < 127) ? gb + 1 : 127;
        float4 cm = *reinterpret_cast<const float4*>(&c[rm1 * 128 + c0]);
        float4 ca = *reinterpret_cast<const float4*>(&c[ga  * 128 + c0]);
        float4 cb = *reinterpret_cast<const float4*>(&c[gb  * 128 + c0]);
        float4 cp = *reinterpret_cast<const float4*>(&c[rp1 * 128 + c0]);
        kkm1x = pack2(0.25f * cm.x * cm.x * invd, 0.25f * cm.y * cm.y * invd);
        kkm1y = pack2(0.25f * cm.z * cm.z * invd, 0.25f * cm.w * cm.w * invd);
        kkax  = pack2(0.25f * ca.x * ca.x * invd, 0.25f * ca.y * ca.y * invd);
        kkay  = pack2(0.25f * ca.z * ca.z * invd, 0.25f * ca.w * ca.w * invd);
        kkbx  = pack2(0.25f * cb.x * cb.x * invd, 0.25f * cb.y * cb.y * invd);
        kkby  = pack2(0.25f * cb.z * cb.z * invd, 0.25f * cb.w * cb.w * invd);
        kkp1x = pack2(0.25f * cp.x * cp.x * invd, 0.25f * cp.y * cp.y * invd);
        kkp1y = pack2(0.25f * cp.z * cp.z * invd, 0.25f * cp.w * cp.w * invd);
    }

    ull y1alo = 0, y1ahi = 0, y1blo = 0, y1bhi = 0;   // time t
    ull y2alo = 0, y2ahi = 0, y2blo = 0, y2bhi = 0;   // time t-1

    // ---- probe decoding (runtime dtype detection: int32 vs int64) ----
    int pxv[NPROBES], pyv[NPROBES];
    {
        int odd_or = probes_i32[1] | probes_i32[3] | probes_i32[5] | probes_i32[7];
        if (odd_or == 0) {
#pragma unroll
            for (int p = 0; p < NPROBES; p++) { pxv[p] = probes_i32[4 * p]; pyv[p] = probes_i32[4 * p + 2]; }
        } else {
#pragma unroll
            for (int p = 0; p < NPROBES; p++) { pxv[p] = probes_i32[2 * p]; pyv[p] = probes_i32[2 * p + 1]; }
        }
    }
    float pacc[NPROBES];
    int   pidx[NPROBES];          // rowsel*4 + comp (rowsel: 0=a, 1=b), or -1
    bool  pown = false;
#pragma unroll
    for (int p = 0; p < NPROBES; p++) {
        pacc[p] = 0.f;
        bool colm = (pyv[p] >= c0) && (pyv[p] < c0 + 4);
        bool mine = colm && (pxv[p] == ga || pxv[p] == gb);
        pidx[p] = mine ? (((pxv[p] == gb) ? 4 : 0) + (pyv[p] - c0)) : -1;
        pown = pown || mine;
    }

    // source (64,64): col 64 -> lane 16, comp 0 (lo of lo pair)
    const bool src_na  = (ga == 64)     && (l == 16);  // my own row a is the source row
    const bool src_gb1 = (gb + 1 == 64) && (l == 16);  // my below-ghost row is the source row

    // roles
    const bool top_edge = (w == 0)          && (rank > 0);
    const bool bot_edge = (w == NWARPS - 1) && (rank < CLUSTER - 1);
    const bool has_up_w = (w > 0);
    const bool has_dn_w = (w < NWARPS - 1);
    const bool row_above_exists = (ga > 0);     // compute ghost row a-1?
    const bool row_below_exists = (gb < 127);   // compute ghost row b+1?

    const uint32_t up_rank = (rank > 0) ? rank - 1 : 0;
    const uint32_t dn_rank = (rank < CLUSTER - 1) ? rank + 1 : rank;
    const uint32_t peer_up_rbuf = mapa_u32(smem_base + OFF_RBUFB, up_rank);  // I fill their rbufB
    const uint32_t peer_up_mbar = mapa_u32(wmbar_base + ((NWARPS - 1) * 2) * 8, up_rank);
    const uint32_t peer_dn_rbuf = mapa_u32(smem_base + OFF_RBUFA, dn_rank);  // I fill their rbufA
    const uint32_t peer_dn_mbar = mapa_u32(wmbar_base + (0 * 2) * 8, dn_rank);

    const uint32_t my_mbar = wmbar_base + (w * 2) * 8;
    const uint32_t up_mbar = wmbar_base + ((w - 1) * 2) * 8;
    const uint32_t dn_mbar = wmbar_base + ((w + 1) * 2) * 8;

    if (l == 0) {
        uint32_t cnt = 0;
        cnt += (has_up_w || rank > 0) ? 1 : 0;
        cnt += (has_dn_w || rank < CLUSTER - 1) ? 1 : 0;
        mbar_init(my_mbar, cnt);
        mbar_init(my_mbar + 8, cnt);
    }
    const bool has_remote = top_edge || bot_edge;

    // row update: above/self/below at time t, y2 at t-1 -> value at t+1
    auto upd = [&](ull ab_lo, ull ab_hi, ull v_lo, ull v_hi,
                   ull bl_lo, ull bl_hi, ull q_lo, ull q_hi,
                   ull kx, ull ky, ull& nv_lo, ull& nv_hi) {
        float vx, vy, vz, vw;
        unpack2(v_lo, vx, vy);
        unpack2(v_hi, vz, vw);
        float lf = __shfl_up_sync(FULLM, vw, 1);
        float rt = __shfl_down_sync(FULLM, vx, 1);
        if (l == 0)  lf = 0.f;
        if (l == 31) rt = 0.f;
        const ull P1 = pack2(lf, vx);
        const ull P2 = pack2(vy, vz);
        const ull P3 = pack2(vw, rt);
        ull lap_lo = fma2(NEG4, v_lo, add2(add2(ab_lo, bl_lo), add2(P1, P2)));
        ull lap_hi = fma2(NEG4, v_hi, add2(add2(ab_hi, bl_hi), add2(P2, P3)));
        nv_lo = fma2(kx, lap_lo, fma2(CY2P, q_lo, TWO2P));
        nv_hi = fma2(ky, lap_hi, fma2(CY2P, q_hi, TWO2P));
    };

    __syncthreads();
    cluster_sync();

    for (int k = 0; k < NBLK; k++) {
        // wait for neighbors' block-(k-1) publication
        if (k > 0) {
            const uint32_t mb = my_mbar + ((k - 1) & 1) * 8;
            const uint32_t ph = ((k - 1) >> 1) & 1;
            if (has_remote) mbar_wait_cluster(mb, ph);
            else            mbar_wait_cta(mb, ph);
        }
        const int rd = (k + 1) & 1;   // buffer holding block k-1 data (zeros for k=0)

        // ---- ghost loads: rows a-2, a-1 (t), a-1 (t-1); b+1, b+2 (t), b+1 (t-1) ----
        ull ga2lo = 0, ga2hi = 0, ga1lo = 0, ga1hi = 0, ha1lo = 0, ha1hi = 0;
        ull gb1lo = 0, gb1hi = 0, gb2lo = 0, gb2hi = 0, hb1lo = 0, hb1hi = 0;
        if (has_up_w) {
            const ull* up = &halo[rd * 2048 + (w - 1) * 256 + 2 * l];
            ulonglong2 h0 = *reinterpret_cast<const ulonglong2*>(up + 0 * 64);   // up a(t)
            ulonglong2 h1 = *reinterpret_cast<const ulonglong2*>(up + 1 * 64);   // up b(t)
            ulonglong2 h3 = *reinterpret_cast<const ulonglong2*>(up + 3 * 64);   // up b(t-1)
            ga2lo = h0.x; ga2hi = h0.y; ga1lo = h1.x; ga1hi = h1.y; ha1lo = h3.x; ha1hi = h3.y;
        } else if (top_edge) {
            const ull* up = &rbufA[rd * 192 + 2 * l];
            ulonglong2 h0 = *reinterpret_cast<const ulonglong2*>(up + 0 * 64);
            ulonglong2 h1 = *reinterpret_cast<const ulonglong2*>(up + 1 * 64);
            ulonglong2 h2 = *reinterpret_cast<const ulonglong2*>(up + 2 * 64);
            ga2lo = h0.x; ga2hi = h0.y; ga1lo = h1.x; ga1hi = h1.y; ha1lo = h2.x; ha1hi = h2.y;
        }
        if (has_dn_w) {
            const ull* dn = &halo[rd * 2048 + (w + 1) * 256 + 2 * l];
            ulonglong2 h0 = *reinterpret_cast<const ulonglong2*>(dn + 0 * 64);   // dn a(t)
            ulonglong2 h1 = *reinterpret_cast<const ulonglong2*>(dn + 1 * 64);   // dn b(t)
            ulonglong2 h2 = *reinterpret_cast<const ulonglong2*>(dn + 2 * 64);   // dn a(t-1)
            gb1lo = h0.x; gb1hi = h0.y; gb2lo = h1.x; gb2hi = h1.y; hb1lo = h2.x; hb1hi = h2.y;
        } else if (bot_edge) {
            const ull* dn = &rbufB[rd * 192 + 2 * l];
            ulonglong2 h0 = *reinterpret_cast<const ulonglong2*>(dn + 0 * 64);
            ulonglong2 h1 = *reinterpret_cast<const ulonglong2*>(dn + 1 * 64);
            ulonglong2 h2 = *reinterpret_cast<const ulonglong2*>(dn + 2 * 64);
            gb1lo = h0.x; gb1hi = h0.y; gb2lo = h1.x; gb2hi = h1.y; hb1lo = h2.x; hb1hi = h2.y;
        }

        const float xt1 = xsh[2 * k];
        const float xt2 = xsh[2 * k + 1];

        // ---- step 1 (time 2k+1): rows a-1, a, b, b+1 ----
        ull ga1p_lo = 0, ga1p_hi = 0, gb1p_lo = 0, gb1p_hi = 0;
        ull na_lo, na_hi, nb_lo, nb_hi;
        if (row_above_exists)
            upd(ga2lo, ga2hi, ga1lo, ga1hi, y1alo, y1ahi, ha1lo, ha1hi,
                kkm1x, kkm1y, ga1p_lo, ga1p_hi);
        upd(ga1lo, ga1hi, y1alo, y1ahi, y1blo, y1bhi, y2alo, y2ahi,
            kkax, kkay, na_lo, na_hi);
        upd(y1alo, y1ahi, y1blo, y1bhi, gb1lo, gb1hi, y2blo, y2bhi,
            kkbx, kkby, nb_lo, nb_hi);
        if (row_below_exists)
            upd(y1blo, y1bhi, gb1lo, gb1hi, gb2lo, gb2hi, hb1lo, hb1hi,
                kkp1x, kkp1y, gb1p_lo, gb1p_hi);

        if (src_na)  { float a2, b2; unpack2(na_lo,   a2, b2); na_lo   = pack2(a2 + xt1, b2); }
        if (src_gb1) { float a2, b2; unpack2(gb1p_lo, a2, b2); gb1p_lo = pack2(a2 + xt1, b2); }

        // ---- step 2 (time 2k+2): rows a, b ----
        ull na2_lo, na2_hi, nb2_lo, nb2_hi;
        upd(ga1p_lo, ga1p_hi, na_lo, na_hi, nb_lo, nb_hi, y1alo, y1ahi,
            kkax, kkay, na2_lo, na2_hi);
        upd(na_lo, na_hi, nb_lo, nb_hi, gb1p_lo, gb1p_hi, y1blo, y1bhi,
            kkbx, kkby, nb2_lo, nb2_hi);

        if (src_na) { float a2, b2; unpack2(na2_lo, a2, b2); na2_lo = pack2(a2 + xt2, b2); }

        // rotate time levels
        y2alo = na_lo;  y2ahi = na_hi;  y2blo = nb_lo;  y2bhi = nb_hi;
        y1alo = na2_lo; y1ahi = na2_hi; y1blo = nb2_lo; y1bhi = nb2_hi;

        // ---- publish + elected arrives (skip after last block) ----
        if (k < NBLK - 1) {
            const int wr = k & 1;
            ull* my = &halo[wr * 2048 + w * 256 + 2 * l];
            ulonglong2 v0; v0.x = na2_lo; v0.y = na2_hi;
            ulonglong2 v1; v1.x = nb2_lo; v1.y = nb2_hi;
            ulonglong2 v2; v2.x = na_lo;  v2.y = na_hi;
            ulonglong2 v3; v3.x = nb_lo;  v3.y = nb_hi;
            *reinterpret_cast<ulonglong2*>(my + 0 * 64) = v0;   // a(t+2)
            *reinterpret_cast<ulonglong2*>(my + 1 * 64) = v1;   // b(t+2)
            *reinterpret_cast<ulonglong2*>(my + 2 * 64) = v2;   // a(t+1)
            *reinterpret_cast<ulonglong2*>(my + 3 * 64) = v3;   // b(t+1)

            if (top_edge) {   // fill up-peer's rbufB: a(t2), b(t2), a(t1)
                const uint32_t base = peer_up_rbuf + (wr * 192 + 2 * l) * 8;
                st_cluster_v2(base + 0 * 512, na2_lo, na2_hi);
                st_cluster_v2(base + 1 * 512, nb2_lo, nb2_hi);
                st_cluster_v2(base + 2 * 512, na_lo,  na_hi);
            }
            if (bot_edge) {   // fill dn-peer's rbufA: a(t2), b(t2), b(t1)
                const uint32_t base = peer_dn_rbuf + (wr * 192 + 2 * l) * 8;
                st_cluster_v2(base + 0 * 512, na2_lo, na2_hi);
                st_cluster_v2(base + 1 * 512, nb2_lo, nb2_hi);
                st_cluster_v2(base + 2 * 512, nb_lo,  nb_hi);
            }

            __syncwarp();   // lanes' stores visible to lane 0 (release propagates them)

            if (l == 0) {
                if (has_up_w)        mbar_arrive_local(up_mbar + wr * 8);
                else if (top_edge)   mbar_arrive_remote(peer_up_mbar + wr * 8);
                if (has_dn_w)        mbar_arrive_local(dn_mbar + wr * 8);
                else if (bot_edge)   mbar_arrive_remote(peer_dn_mbar + wr * 8);
            }
        }

        // ---- probe accumulation at times 2k+1 and 2k+2 (own rows only) ----
        if (pown) {
#pragma unroll
            for (int p = 0; p < NPROBES; p++) {
                if (pidx[p] >= 0) {
                    float a1, b1, v1f = 0.f, v2f = 0.f;
                    switch (pidx[p]) {
                        case 0: unpack2(na_lo, a1, b1); v1f = a1; unpack2(na2_lo, a1, b1); v2f = a1; break;
                        case 1: unpack2(na_lo, a1, b1); v1f = b1; unpack2(na2_lo, a1, b1); v2f = b1; break;
                        case 2: unpack2(na_hi, a1, b1); v1f = a1; unpack2(na2_hi, a1, b1); v2f = a1; break;
                        case 3: unpack2(na_hi, a1, b1); v1f = b1; unpack2(na2_hi, a1, b1); v2f = b1; break;
                        case 4: unpack2(nb_lo, a1, b1); v1f = a1; unpack2(nb2_lo, a1, b1); v2f = a1; break;
                        case 5: unpack2(nb_lo, a1, b1); v1f = b1; unpack2(nb2_lo, a1, b1); v2f = b1; break;
                        case 6: unpack2(nb_hi, a1, b1); v1f = a1; unpack2(nb2_hi, a1, b1); v2f = a1; break;
                        case 7: unpack2(nb_hi, a1, b1); v1f = b1; unpack2(nb2_hi, a1, b1); v2f = b1; break;
                    }
                    pacc[p] += v1f * v1f + v2f * v2f;
                }
            }
        }
    }

#pragma unroll
    for (int p = 0; p < NPROBES; p++)
        if (pidx[p] >= 0) atomicAdd(&g_psum[p], pacc[p]);

    // fused finalization: last of 64 CTAs reduces, writes out, resets globals
    __syncthreads();
    __threadfence();
    if (tid == 0) {
        unsigned ticket = atomicAdd(&g_ticket, 1u);
        if (ticket == NCTAS - 1) {
            float v[NPROBES];
            float s = 0.f;
#pragma unroll
            for (int p = 0; p < NPROBES; p++) { v[p] = atomicAdd(&g_psum[p], 0.0f); s += v[p]; }
#pragma unroll
            for (int p = 0; p < NPROBES; p++) {
                out[p] = v[p] / s;
                atomicExch(&g_psum[p], 0.0f);
            }
            atomicExch(&g_ticket, 0u);
        }
    }
}

extern "C" void kernel_launch(void* const* d_in, const int* in_sizes, int n_in,
                              void* d_out, int out_size)
{
    const float* x      = (const float*)d_in[0];   // (256, 8) f32
    const float* c      = (const float*)d_in[1];   // (128, 128) f32
    const int*   probes = (const int*)d_in[2];     // (4, 2) i32/i64 — detected in-kernel
    float*       out    = (float*)d_out;           // (4,) f32

    cudaFuncSetAttribute(wave_fused_kernel,
                         cudaFuncAttributeMaxDynamicSharedMemorySize, SMEM_BYTES);

    wave_fused_kernel<<<NCTAS, NTHREADS, SMEM_BYTES>>>(x, c, probes, out);
}